// round 1
// baseline (speedup 1.0000x reference)
#include <cuda_runtime.h>
#include <math.h>
#include <stdint.h>

// Problem constants
#define TT   512
#define BB   64
#define HH   1024
#define NCTA 128
#define NTHR 256

// Persistent scratch (device globals: allocation-free rule)
__device__ float g_pre[(size_t)TT * HH * BB];   // [t][h][b]  (pre-activation of layer0 input term, transposed for coalesced step reads)
__device__ float g_h0[2][HH * BB];              // [k][b] double-buffered
__device__ float g_h1[2][HH * BB];
__device__ unsigned long long g_arrive;                  // ticket-barrier arrivals (monotonic across graph replays)
__device__ volatile unsigned long long g_release;        // ticket-barrier release generation

// ---------------------------------------------------------------------------
// Grid-wide ticket barrier. All NCTA CTAs are resident (1 CTA/SM, 128 <= 148),
// counters are monotonic so no reset is needed between graph replays.
// ---------------------------------------------------------------------------
__device__ __forceinline__ void gsync()
{
    __syncthreads();
    if (threadIdx.x == 0) {
        __threadfence();  // make this CTA's stcg writes visible before arriving
        unsigned long long old = atomicAdd(&g_arrive, 1ULL);
        unsigned long long target = old / NCTA + 1ULL;
        if ((old % NCTA) == (NCTA - 1)) {
            __threadfence();
            g_release = target;
        } else {
            while (g_release < target) { __nanosleep(40); }
        }
        __threadfence();
    }
    __syncthreads();
}

// ---------------------------------------------------------------------------
// Kernel A: g_pre[t][j][b] = sum_k X[t][b][k] * Wih0[j][k] + bih0[j] + bhh0[j]
// Classic 128x64 tile, 8x4 per-thread microtile, fp32.
// ---------------------------------------------------------------------------
__global__ void __launch_bounds__(256) pregemm(const float* __restrict__ X,
                                               const float* __restrict__ W,
                                               const float* __restrict__ bih,
                                               const float* __restrict__ bhh)
{
    __shared__ float As[16][132];  // [k][m], padded
    __shared__ float Bs[16][68];   // [k][n], padded
    const int tid = threadIdx.x;
    const int m0 = blockIdx.y * 128;
    const int n0 = blockIdx.x * 64;
    const int tx = tid & 15;   // n micro (4 cols)
    const int ty = tid >> 4;   // m micro (8 rows)

    float acc[8][4];
#pragma unroll
    for (int i = 0; i < 8; i++)
#pragma unroll
        for (int j = 0; j < 4; j++) acc[i][j] = 0.f;

    for (int k0 = 0; k0 < 1024; k0 += 16) {
#pragma unroll
        for (int i = 0; i < 2; i++) {
            int q  = tid + i * 256;        // float4 id, 512 total (128 rows x 4)
            int m  = q >> 2;
            int kq = (q & 3) << 2;
            float4 v = __ldg((const float4*)&X[(size_t)(m0 + m) * 1024 + k0 + kq]);
            As[kq + 0][m] = v.x; As[kq + 1][m] = v.y;
            As[kq + 2][m] = v.z; As[kq + 3][m] = v.w;
        }
        {
            int n  = tid >> 2;
            int kq = (tid & 3) << 2;
            float4 v = __ldg((const float4*)&W[(size_t)(n0 + n) * 1024 + k0 + kq]);
            Bs[kq + 0][n] = v.x; Bs[kq + 1][n] = v.y;
            Bs[kq + 2][n] = v.z; Bs[kq + 3][n] = v.w;
        }
        __syncthreads();
#pragma unroll
        for (int kk = 0; kk < 16; kk++) {
            float a[8], b[4];
            *(float4*)&a[0] = *(const float4*)&As[kk][ty * 8];
            *(float4*)&a[4] = *(const float4*)&As[kk][ty * 8 + 4];
            *(float4*)&b[0] = *(const float4*)&Bs[kk][tx * 4];
#pragma unroll
            for (int i = 0; i < 8; i++)
#pragma unroll
                for (int j = 0; j < 4; j++)
                    acc[i][j] = fmaf(a[i], b[j], acc[i][j]);
        }
        __syncthreads();
    }

#pragma unroll
    for (int i = 0; i < 8; i++) {
        int gm = m0 + ty * 8 + i;
        int t  = gm >> 6;
        int b  = gm & 63;
#pragma unroll
        for (int j = 0; j < 4; j++) {
            int gn = n0 + tx * 4 + j;
            g_pre[((size_t)t * 1024 + gn) * 64 + b] =
                acc[i][j] + __ldg(&bih[gn]) + __ldg(&bhh[gn]);
        }
    }
}

// ---------------------------------------------------------------------------
// Kernel I: initialize transposed h buffers from h_0 [2][B][H]
// ---------------------------------------------------------------------------
__global__ void init_h(const float* __restrict__ h0in)
{
    int e = blockIdx.x * blockDim.x + threadIdx.x;  // 2*64*1024 total
    if (e < 2 * BB * HH) {
        int l = e >> 16;
        int r = e & 65535;
        int b = r >> 10;
        int k = r & 1023;
        float* dst = l ? g_h1[0] : g_h0[0];
        dst[k * 64 + b] = h0in[e];
    }
}

// ---------------------------------------------------------------------------
// accum_tile: acc[4][4] += (h[b0..b0+3] dot W-slice cols j0..j0+3) over K=1024.
// h streamed gmem(L2)->smem in 8 chunks of 128 k (register-prefetched),
// split-K: warp-group g (tid>>5) handles k = c*128 + g*16 + [0,16).
// ---------------------------------------------------------------------------
__device__ __forceinline__ void accum_tile(const float* __restrict__ hbuf,  // [H][64] gmem
                                           const float* __restrict__ wt,   // smem [H][8] (transposed slice)
                                           float*       hs,                // smem staging, 8192 floats
                                           float acc[4][4], int b0, int j0)
{
    const float4* src = (const float4*)hbuf;  // 2048 float4 per 128-k chunk
    float4 pf[8];
#pragma unroll
    for (int i = 0; i < 8; i++) pf[i] = __ldcg(src + threadIdx.x + i * 256);

    const int g = threadIdx.x >> 5;
    for (int c = 0; c < 8; c++) {
        __syncthreads();   // previous consumers of hs are done
#pragma unroll
        for (int i = 0; i < 8; i++) ((float4*)hs)[threadIdx.x + i * 256] = pf[i];
        __syncthreads();
        if (c < 7) {
            const float4* nsrc = src + (size_t)(c + 1) * 2048;
#pragma unroll
            for (int i = 0; i < 8; i++) pf[i] = __ldcg(nsrc + threadIdx.x + i * 256);
        }
#pragma unroll
        for (int kk = 0; kk < 16; kk++) {
            int kl = g * 16 + kk;               // k within chunk
            float4 hv = *(const float4*)(hs + kl * 64 + b0);
            float4 wv = *(const float4*)(wt + (size_t)(c * 128 + kl) * 8 + j0);
            float hvv[4] = { hv.x, hv.y, hv.z, hv.w };
            float wvv[4] = { wv.x, wv.y, wv.z, wv.w };
#pragma unroll
            for (int j = 0; j < 4; j++)
#pragma unroll
                for (int b = 0; b < 4; b++)
                    acc[j][b] = fmaf(wvv[j], hvv[b], acc[j][b]);
        }
    }
}

__device__ __forceinline__ void store_red(float* red, float acc[4][4])
{
    int g = threadIdx.x >> 5, lane = threadIdx.x & 31;
    int bt = lane & 15, jt = lane >> 4;
#pragma unroll
    for (int j = 0; j < 4; j++) {
        float4 v = make_float4(acc[j][0], acc[j][1], acc[j][2], acc[j][3]);
        *(float4*)&red[(g * 8 + jt * 4 + j) * 64 + bt * 4] = v;
    }
}

// ---------------------------------------------------------------------------
// Kernel B: persistent recurrent loop. 128 CTAs x 256 threads.
// CTA c owns output columns [c*8, c*8+8) of every in-loop matrix; the three
// 8x1024 weight slices (96 KB) live in SMEM for the whole kernel.
// ---------------------------------------------------------------------------
__global__ void __launch_bounds__(NTHR) rnn_persist(
    const float* __restrict__ Whh0, const float* __restrict__ Wih1,
    const float* __restrict__ Whh1, const float* __restrict__ bih1,
    const float* __restrict__ bhh1, float* __restrict__ out)
{
    extern __shared__ float smem[];
    float* wt0   = smem;            // 8192 floats  W_hh0 slice, [k][8]
    float* wt1   = smem + 8192;     //              W_ih1 slice
    float* wt2   = smem + 16384;    //              W_hh1 slice
    float* hs    = smem + 24576;    // 8192 floats staging; aliased as 4096-float red buffer
    float* bias1 = smem + 32768;    // 8 floats

    const int tid   = threadIdx.x;
    const int jbase = blockIdx.x * 8;

    // Load weight slices once (transposed [k][jj])
    for (int idx = tid; idx < 8192; idx += NTHR) {
        int jj = idx >> 10, k = idx & 1023;
        wt0[k * 8 + jj] = __ldg(&Whh0[(size_t)(jbase + jj) * 1024 + k]);
        wt1[k * 8 + jj] = __ldg(&Wih1[(size_t)(jbase + jj) * 1024 + k]);
        wt2[k * 8 + jj] = __ldg(&Whh1[(size_t)(jbase + jj) * 1024 + k]);
    }
    if (tid < 8) bias1[tid] = __ldg(&bih1[jbase + tid]) + __ldg(&bhh1[jbase + tid]);
    __syncthreads();

    const int lane = tid & 31;
    const int b0 = (lane & 15) * 4;
    const int j0 = (lane >> 4) * 4;

    for (int t = 0; t < TT; t++) {
        const int cur = t & 1, nxt = cur ^ 1;

        // ---------- Phase 1: h0_new = tanh(pre[t] + h0_old @ Whh0^T) ----------
        {
            float acc[4][4];
#pragma unroll
            for (int j = 0; j < 4; j++)
#pragma unroll
                for (int b = 0; b < 4; b++) acc[j][b] = 0.f;

            accum_tile(g_h0[cur], wt0, hs, acc, b0, j0);
            __syncthreads();
            store_red(hs, acc);
            __syncthreads();
#pragma unroll
            for (int e2 = 0; e2 < 2; e2++) {
                int e = tid + e2 * NTHR;
                int j = e >> 6, b = e & 63;
                float s = 0.f;
#pragma unroll
                for (int g = 0; g < 8; g++) s += hs[(g * 8 + j) * 64 + b];
                int jg = jbase + j;
                float v = s + __ldcg(&g_pre[((size_t)t * 1024 + jg) * 64 + b]);
                __stcg(&g_h0[nxt][jg * 64 + b], tanhf(v));
            }
            gsync();
        }

        // ---------- Phase 2: h1_new = tanh(h0_new @ Wih1^T + h1_old @ Whh1^T + biases) ----------
        {
            float acc[4][4];
#pragma unroll
            for (int j = 0; j < 4; j++)
#pragma unroll
                for (int b = 0; b < 4; b++) acc[j][b] = 0.f;

            accum_tile(g_h0[nxt], wt1, hs, acc, b0, j0);
            accum_tile(g_h1[cur], wt2, hs, acc, b0, j0);
            __syncthreads();
            store_red(hs, acc);
            __syncthreads();
#pragma unroll
            for (int e2 = 0; e2 < 2; e2++) {
                int e = tid + e2 * NTHR;
                int j = e >> 6, b = e & 63;
                float s = 0.f;
#pragma unroll
                for (int g = 0; g < 8; g++) s += hs[(g * 8 + j) * 64 + b];
                int jg = jbase + j;
                float h = tanhf(s + bias1[j]);
                __stcg(&g_h1[nxt][jg * 64 + b], h);
                out[((size_t)t * 64 + b) * 1024 + jg] = h;   // outputs[t][b][h]
            }
            gsync();
        }
    }

    // Final h_n: after 512 steps (even), final state sits in buffer index 0.
    for (int e = blockIdx.x * NTHR + tid; e < 2 * BB * HH; e += NCTA * NTHR) {
        int l = e >> 16;
        int r = e & 65535;
        int b = r >> 10;
        int k = r & 1023;
        const float* src = l ? g_h1[0] : g_h0[0];
        out[(size_t)TT * BB * HH + e] = __ldcg(&src[k * 64 + b]);
    }
}

// ---------------------------------------------------------------------------
extern "C" void kernel_launch(void* const* d_in, const int* in_sizes, int n_in,
                              void* d_out, int out_size)
{
    const float* input = (const float*)d_in[0];
    const float* h0in  = (const float*)d_in[1];
    const float* Wih0  = (const float*)d_in[2];
    const float* bih0  = (const float*)d_in[3];
    const float* Whh0  = (const float*)d_in[4];
    const float* bhh0  = (const float*)d_in[5];
    const float* Wih1  = (const float*)d_in[6];
    const float* bih1  = (const float*)d_in[7];
    const float* Whh1  = (const float*)d_in[8];
    const float* bhh1  = (const float*)d_in[9];
    float* out = (float*)d_out;

    const int smem_bytes = (24576 + 8192 + 8) * 4;  // 131104 B
    cudaFuncSetAttribute(rnn_persist, cudaFuncAttributeMaxDynamicSharedMemorySize, smem_bytes);

    pregemm<<<dim3(16, 256), 256>>>(input, Wih0, bih0, bhh0);
    init_h<<<512, 256>>>(h0in);
    rnn_persist<<<NCTA, NTHR, smem_bytes>>>(Whh0, Wih1, Whh1, bih1, bhh1, out);
}

// round 2
// speedup vs baseline: 1.0006x; 1.0006x over previous
#include <cuda_runtime.h>
#include <math.h>
#include <stdint.h>

// Problem constants
#define TT   512
#define BB   64
#define HH   1024
#define NCTA 128
#define NTHR 256

// Persistent scratch (device globals: allocation-free rule)
__device__ float g_pre[(size_t)TT * HH * BB];   // [t][h][b]  (pre-activation of layer0 input term, transposed for coalesced step reads)
__device__ float g_h0[2][HH * BB];              // [k][b] double-buffered
__device__ float g_h1[2][HH * BB];
__device__ unsigned long long g_arrive;                  // ticket-barrier arrivals (monotonic across graph replays)
__device__ volatile unsigned long long g_release;        // ticket-barrier release generation

// ---------------------------------------------------------------------------
// Grid-wide ticket barrier. All NCTA CTAs are resident (1 CTA/SM, 128 <= 148),
// counters are monotonic so no reset is needed between graph replays.
// ---------------------------------------------------------------------------
__device__ __forceinline__ void gsync()
{
    __syncthreads();
    if (threadIdx.x == 0) {
        __threadfence();  // make this CTA's stcg writes visible before arriving
        unsigned long long old = atomicAdd(&g_arrive, 1ULL);
        unsigned long long target = old / NCTA + 1ULL;
        if ((old % NCTA) == (NCTA - 1)) {
            __threadfence();
            g_release = target;
        } else {
            while (g_release < target) { __nanosleep(40); }
        }
        __threadfence();
    }
    __syncthreads();
}

// ---------------------------------------------------------------------------
// Kernel A: g_pre[t][j][b] = sum_k X[t][b][k] * Wih0[j][k] + bih0[j] + bhh0[j]
// Classic 128x64 tile, 8x4 per-thread microtile, fp32.
// ---------------------------------------------------------------------------
__global__ void __launch_bounds__(256) pregemm(const float* __restrict__ X,
                                               const float* __restrict__ W,
                                               const float* __restrict__ bih,
                                               const float* __restrict__ bhh)
{
    __shared__ float As[16][132];  // [k][m], padded
    __shared__ float Bs[16][68];   // [k][n], padded
    const int tid = threadIdx.x;
    const int m0 = blockIdx.y * 128;
    const int n0 = blockIdx.x * 64;
    const int tx = tid & 15;   // n micro (4 cols)
    const int ty = tid >> 4;   // m micro (8 rows)

    float acc[8][4];
#pragma unroll
    for (int i = 0; i < 8; i++)
#pragma unroll
        for (int j = 0; j < 4; j++) acc[i][j] = 0.f;

    for (int k0 = 0; k0 < 1024; k0 += 16) {
#pragma unroll
        for (int i = 0; i < 2; i++) {
            int q  = tid + i * 256;        // float4 id, 512 total (128 rows x 4)
            int m  = q >> 2;
            int kq = (q & 3) << 2;
            float4 v = __ldg((const float4*)&X[(size_t)(m0 + m) * 1024 + k0 + kq]);
            As[kq + 0][m] = v.x; As[kq + 1][m] = v.y;
            As[kq + 2][m] = v.z; As[kq + 3][m] = v.w;
        }
        {
            int n  = tid >> 2;
            int kq = (tid & 3) << 2;
            float4 v = __ldg((const float4*)&W[(size_t)(n0 + n) * 1024 + k0 + kq]);
            Bs[kq + 0][n] = v.x; Bs[kq + 1][n] = v.y;
            Bs[kq + 2][n] = v.z; Bs[kq + 3][n] = v.w;
        }
        __syncthreads();
#pragma unroll
        for (int kk = 0; kk < 16; kk++) {
            float a[8], b[4];
            *(float4*)&a[0] = *(const float4*)&As[kk][ty * 8];
            *(float4*)&a[4] = *(const float4*)&As[kk][ty * 8 + 4];
            *(float4*)&b[0] = *(const float4*)&Bs[kk][tx * 4];
#pragma unroll
            for (int i = 0; i < 8; i++)
#pragma unroll
                for (int j = 0; j < 4; j++)
                    acc[i][j] = fmaf(a[i], b[j], acc[i][j]);
        }
        __syncthreads();
    }

#pragma unroll
    for (int i = 0; i < 8; i++) {
        int gm = m0 + ty * 8 + i;
        int t  = gm >> 6;
        int b  = gm & 63;
#pragma unroll
        for (int j = 0; j < 4; j++) {
            int gn = n0 + tx * 4 + j;
            g_pre[((size_t)t * 1024 + gn) * 64 + b] =
                acc[i][j] + __ldg(&bih[gn]) + __ldg(&bhh[gn]);
        }
    }
}

// ---------------------------------------------------------------------------
// Kernel I: initialize transposed h buffers from h_0 [2][B][H]
// ---------------------------------------------------------------------------
__global__ void init_h(const float* __restrict__ h0in)
{
    int e = blockIdx.x * blockDim.x + threadIdx.x;  // 2*64*1024 total
    if (e < 2 * BB * HH) {
        int l = e >> 16;
        int r = e & 65535;
        int b = r >> 10;
        int k = r & 1023;
        float* dst = l ? g_h1[0] : g_h0[0];
        dst[k * 64 + b] = h0in[e];
    }
}

// ---------------------------------------------------------------------------
// accum_tile: acc[4][4] += (h[b0..b0+3] dot W-slice cols j0..j0+3) over K=1024.
// h streamed gmem(L2)->smem in 8 chunks of 128 k (register-prefetched),
// split-K: warp-group g (tid>>5) handles k = c*128 + g*16 + [0,16).
// ---------------------------------------------------------------------------
__device__ __forceinline__ void accum_tile(const float* __restrict__ hbuf,  // [H][64] gmem
                                           const float* __restrict__ wt,   // smem [H][8] (transposed slice)
                                           float*       hs,                // smem staging, 8192 floats
                                           float acc[4][4], int b0, int j0)
{
    const float4* src = (const float4*)hbuf;  // 2048 float4 per 128-k chunk
    float4 pf[8];
#pragma unroll
    for (int i = 0; i < 8; i++) pf[i] = __ldcg(src + threadIdx.x + i * 256);

    const int g = threadIdx.x >> 5;
    for (int c = 0; c < 8; c++) {
        __syncthreads();   // previous consumers of hs are done
#pragma unroll
        for (int i = 0; i < 8; i++) ((float4*)hs)[threadIdx.x + i * 256] = pf[i];
        __syncthreads();
        if (c < 7) {
            const float4* nsrc = src + (size_t)(c + 1) * 2048;
#pragma unroll
            for (int i = 0; i < 8; i++) pf[i] = __ldcg(nsrc + threadIdx.x + i * 256);
        }
#pragma unroll
        for (int kk = 0; kk < 16; kk++) {
            int kl = g * 16 + kk;               // k within chunk
            float4 hv = *(const float4*)(hs + kl * 64 + b0);
            float4 wv = *(const float4*)(wt + (size_t)(c * 128 + kl) * 8 + j0);
            float hvv[4] = { hv.x, hv.y, hv.z, hv.w };
            float wvv[4] = { wv.x, wv.y, wv.z, wv.w };
#pragma unroll
            for (int j = 0; j < 4; j++)
#pragma unroll
                for (int b = 0; b < 4; b++)
                    acc[j][b] = fmaf(wvv[j], hvv[b], acc[j][b]);
        }
    }
}

__device__ __forceinline__ void store_red(float* red, float acc[4][4])
{
    int g = threadIdx.x >> 5, lane = threadIdx.x & 31;
    int bt = lane & 15, jt = lane >> 4;
#pragma unroll
    for (int j = 0; j < 4; j++) {
        float4 v = make_float4(acc[j][0], acc[j][1], acc[j][2], acc[j][3]);
        *(float4*)&red[(g * 8 + jt * 4 + j) * 64 + bt * 4] = v;
    }
}

// ---------------------------------------------------------------------------
// Kernel B: persistent recurrent loop. 128 CTAs x 256 threads.
// CTA c owns output columns [c*8, c*8+8) of every in-loop matrix; the three
// 8x1024 weight slices (96 KB) live in SMEM for the whole kernel.
// ---------------------------------------------------------------------------
__global__ void __launch_bounds__(NTHR) rnn_persist(
    const float* __restrict__ Whh0, const float* __restrict__ Wih1,
    const float* __restrict__ Whh1, const float* __restrict__ bih1,
    const float* __restrict__ bhh1, float* __restrict__ out)
{
    extern __shared__ float smem[];
    float* wt0   = smem;            // 8192 floats  W_hh0 slice, [k][8]
    float* wt1   = smem + 8192;     //              W_ih1 slice
    float* wt2   = smem + 16384;    //              W_hh1 slice
    float* hs    = smem + 24576;    // 8192 floats staging; aliased as 4096-float red buffer
    float* bias1 = smem + 32768;    // 8 floats

    const int tid   = threadIdx.x;
    const int jbase = blockIdx.x * 8;

    // Load weight slices once (transposed [k][jj])
    for (int idx = tid; idx < 8192; idx += NTHR) {
        int jj = idx >> 10, k = idx & 1023;
        wt0[k * 8 + jj] = __ldg(&Whh0[(size_t)(jbase + jj) * 1024 + k]);
        wt1[k * 8 + jj] = __ldg(&Wih1[(size_t)(jbase + jj) * 1024 + k]);
        wt2[k * 8 + jj] = __ldg(&Whh1[(size_t)(jbase + jj) * 1024 + k]);
    }
    if (tid < 8) bias1[tid] = __ldg(&bih1[jbase + tid]) + __ldg(&bhh1[jbase + tid]);
    __syncthreads();

    const int lane = tid & 31;
    const int b0 = (lane & 15) * 4;
    const int j0 = (lane >> 4) * 4;

    for (int t = 0; t < TT; t++) {
        const int cur = t & 1, nxt = cur ^ 1;

        // ---------- Phase 1: h0_new = tanh(pre[t] + h0_old @ Whh0^T) ----------
        {
            float acc[4][4];
#pragma unroll
            for (int j = 0; j < 4; j++)
#pragma unroll
                for (int b = 0; b < 4; b++) acc[j][b] = 0.f;

            accum_tile(g_h0[cur], wt0, hs, acc, b0, j0);
            __syncthreads();
            store_red(hs, acc);
            __syncthreads();
#pragma unroll
            for (int e2 = 0; e2 < 2; e2++) {
                int e = tid + e2 * NTHR;
                int j = e >> 6, b = e & 63;
                float s = 0.f;
#pragma unroll
                for (int g = 0; g < 8; g++) s += hs[(g * 8 + j) * 64 + b];
                int jg = jbase + j;
                float v = s + __ldcg(&g_pre[((size_t)t * 1024 + jg) * 64 + b]);
                __stcg(&g_h0[nxt][jg * 64 + b], tanhf(v));
            }
            gsync();
        }

        // ---------- Phase 2: h1_new = tanh(h0_new @ Wih1^T + h1_old @ Whh1^T + biases) ----------
        {
            float acc[4][4];
#pragma unroll
            for (int j = 0; j < 4; j++)
#pragma unroll
                for (int b = 0; b < 4; b++) acc[j][b] = 0.f;

            accum_tile(g_h0[nxt], wt1, hs, acc, b0, j0);
            accum_tile(g_h1[cur], wt2, hs, acc, b0, j0);
            __syncthreads();
            store_red(hs, acc);
            __syncthreads();
#pragma unroll
            for (int e2 = 0; e2 < 2; e2++) {
                int e = tid + e2 * NTHR;
                int j = e >> 6, b = e & 63;
                float s = 0.f;
#pragma unroll
                for (int g = 0; g < 8; g++) s += hs[(g * 8 + j) * 64 + b];
                int jg = jbase + j;
                float h = tanhf(s + bias1[j]);
                __stcg(&g_h1[nxt][jg * 64 + b], h);
                out[((size_t)t * 64 + b) * 1024 + jg] = h;   // outputs[t][b][h]
            }
            gsync();
        }
    }

    // Final h_n: after 512 steps (even), final state sits in buffer index 0.
    for (int e = blockIdx.x * NTHR + tid; e < 2 * BB * HH; e += NCTA * NTHR) {
        int l = e >> 16;
        int r = e & 65535;
        int b = r >> 10;
        int k = r & 1023;
        const float* src = l ? g_h1[0] : g_h0[0];
        out[(size_t)TT * BB * HH + e] = __ldcg(&src[k * 64 + b]);
    }
}

// ---------------------------------------------------------------------------
extern "C" void kernel_launch(void* const* d_in, const int* in_sizes, int n_in,
                              void* d_out, int out_size)
{
    const float* input = (const float*)d_in[0];
    const float* h0in  = (const float*)d_in[1];
    const float* Wih0  = (const float*)d_in[2];
    const float* bih0  = (const float*)d_in[3];
    const float* Whh0  = (const float*)d_in[4];
    const float* bhh0  = (const float*)d_in[5];
    const float* Wih1  = (const float*)d_in[6];
    const float* bih1  = (const float*)d_in[7];
    const float* Whh1  = (const float*)d_in[8];
    const float* bhh1  = (const float*)d_in[9];
    float* out = (float*)d_out;

    const int smem_bytes = (24576 + 8192 + 8) * 4;  // 131104 B
    cudaFuncSetAttribute(rnn_persist, cudaFuncAttributeMaxDynamicSharedMemorySize, smem_bytes);

    pregemm<<<dim3(16, 256), 256>>>(input, Wih0, bih0, bhh0);
    init_h<<<512, 256>>>(h0in);
    rnn_persist<<<NCTA, NTHR, smem_bytes>>>(Whh0, Wih1, Whh1, bih1, bhh1, out);
}